// round 6
// baseline (speedup 1.0000x reference)
#include <cuda_runtime.h>
#include <cuda_bf16.h>
#include <math.h>
#include <stdint.h>

#define Ldim 2048
#define Nb   4
#define E    768
#define H    12
#define HD   64
#define BH   (Nb*H)         /* 48 */
#define Mrows (Ldim*Nb)     /* 8192 */
#define EE   (E*E)          /* 589824 */

// ---------------- scratch (static device globals; no runtime allocation) ----
__device__ float g_weff[4*EE];
__device__ float g_v[Mrows*E];
__device__ float g_o[Mrows*E];
// bf16 hi/lo split buffers: q,k as [bh][l][64]; v transposed as [bh][d][L]
__device__ __nv_bfloat16 g_qh[BH*Ldim*HD], g_ql[BH*Ldim*HD];
__device__ __nv_bfloat16 g_kh[BH*Ldim*HD], g_kl[BH*Ldim*HD];
__device__ __nv_bfloat16 g_vth[BH*HD*Ldim], g_vtl[BH*HD*Ldim];

// ============================ helpers ========================================
__device__ __forceinline__ uint32_t smem_u32(const void* p) {
    uint32_t a;
    asm("{ .reg .u64 t; cvta.to.shared.u64 t, %1; cvt.u32.u64 %0, t; }"
        : "=r"(a) : "l"(p));
    return a;
}
__device__ __forceinline__ float ex2f(float x) {
    float y; asm("ex2.approx.f32 %0, %1;" : "=f"(y) : "f"(x)); return y;
}
#define STS128(addr, r0, r1, r2, r3) \
    asm volatile("st.shared.v4.b32 [%0], {%1, %2, %3, %4};" \
                 :: "r"(addr), "r"(r0), "r"(r1), "r"(r2), "r"(r3) : "memory")

__device__ __forceinline__ void cpa16(uint32_t dst, const void* src) {
    asm volatile("cp.async.cg.shared.global [%0], [%1], 16;"
                 :: "r"(dst), "l"(src) : "memory");
}
#define CP_COMMIT() asm volatile("cp.async.commit_group;" ::: "memory")
#define CP_WAIT1()  asm volatile("cp.async.wait_group 1;" ::: "memory")
#define CP_WAIT0()  asm volatile("cp.async.wait_group 0;" ::: "memory")

__device__ __forceinline__ void ldm_x4(uint32_t* r, uint32_t addr) {
    asm volatile("ldmatrix.sync.aligned.m8n8.x4.shared.b16 {%0,%1,%2,%3}, [%4];"
                 : "=r"(r[0]), "=r"(r[1]), "=r"(r[2]), "=r"(r[3]) : "r"(addr));
}
__device__ __forceinline__ void mma16816(float* c, const uint32_t* a,
                                         const uint32_t* b) {
    asm volatile(
        "mma.sync.aligned.m16n8k16.row.col.f32.bf16.bf16.f32 "
        "{%0,%1,%2,%3}, {%4,%5,%6,%7}, {%8,%9}, {%0,%1,%2,%3};"
        : "+f"(c[0]), "+f"(c[1]), "+f"(c[2]), "+f"(c[3])
        : "r"(a[0]), "r"(a[1]), "r"(a[2]), "r"(a[3]), "r"(b[0]), "r"(b[1]));
}
// split a pair of floats into bf16 hi and lo packed words (elem0 in low bits)
__device__ __forceinline__ void split2(float a, float b, uint32_t& hi, uint32_t& lo) {
    __nv_bfloat162 h = __floats2bfloat162_rn(a, b);
    float la = a - __bfloat162float(h.x);
    float lb = b - __bfloat162float(h.y);
    __nv_bfloat162 l = __floats2bfloat162_rn(la, lb);
    hi = *reinterpret_cast<uint32_t*>(&h);
    lo = *reinterpret_cast<uint32_t*>(&l);
}

// ---------------- W_eff = W + up @ down -------------------------------------
__global__ void weff_kernel(const float* __restrict__ inW,
                            const float* __restrict__ outW,
                            const float* __restrict__ qd, const float* __restrict__ qu,
                            const float* __restrict__ kd, const float* __restrict__ ku,
                            const float* __restrict__ vd, const float* __restrict__ vu,
                            const float* __restrict__ od, const float* __restrict__ ou)
{
    int z = blockIdx.y;
    int idx = blockIdx.x * 256 + threadIdx.x;
    int e = idx / E;
    int k = idx - e * E;
    const float* W  = (z < 3) ? (inW + z * EE) : outW;
    const float* dn = (z == 0) ? qd : (z == 1) ? kd : (z == 2) ? vd : od;
    const float* up = (z == 0) ? qu : (z == 1) ? ku : (z == 2) ? vu : ou;
    float s = 0.f;
#pragma unroll
    for (int r = 0; r < 16; r++) s += up[e * 16 + r] * dn[r * E + k];
    g_weff[z * EE + idx] = W[idx] + s;
}

// ---------------- 128x128x8 register-tiled fp32 GEMM ------------------------
// do_split: z<2 outputs go directly to bf16 hi/lo split buffers [bh][l][64]
__global__ void __launch_bounds__(256, 2) gemm_proj(
    const float* __restrict__ x0, const float* __restrict__ x1, const float* __restrict__ x2,
    const float* __restrict__ Wbase, const float* __restrict__ bias_base,
    float* __restrict__ y0, float* __restrict__ y1, float* __restrict__ y2,
    int qz, int do_split)
{
    int z = blockIdx.z;
    const float* x = (z == 0) ? x0 : (z == 1) ? x1 : x2;
    float*       y = (z == 0) ? y0 : (z == 1) ? y1 : y2;
    const float* W = Wbase + (size_t)z * EE;
    const float* bias = bias_base + z * E;

    int m0 = blockIdx.y * 128;
    int e0 = blockIdx.x * 128;

    __shared__ float As[8][128];
    __shared__ float Bs[8][128];

    float acc[8][8];
#pragma unroll
    for (int i = 0; i < 8; i++)
#pragma unroll
        for (int j = 0; j < 8; j++) acc[i][j] = 0.f;

    int tid = threadIdx.x;
    int lr = tid >> 1;
    int lc = (tid & 1) * 4;
    int ty = tid >> 4, tx = tid & 15;

    for (int k0 = 0; k0 < E; k0 += 8) {
        float4 av = *(const float4*)(x + (size_t)(m0 + lr) * E + k0 + lc);
        float4 bv = *(const float4*)(W + (size_t)(e0 + lr) * E + k0 + lc);
        __syncthreads();
        As[lc + 0][lr] = av.x; As[lc + 1][lr] = av.y; As[lc + 2][lr] = av.z; As[lc + 3][lr] = av.w;
        Bs[lc + 0][lr] = bv.x; Bs[lc + 1][lr] = bv.y; Bs[lc + 2][lr] = bv.z; Bs[lc + 3][lr] = bv.w;
        __syncthreads();
#pragma unroll
        for (int kt = 0; kt < 8; kt++) {
            float a[8], b[8];
            float4 t;
            t = *(const float4*)&As[kt][ty * 4];      a[0]=t.x; a[1]=t.y; a[2]=t.z; a[3]=t.w;
            t = *(const float4*)&As[kt][64 + ty * 4]; a[4]=t.x; a[5]=t.y; a[6]=t.z; a[7]=t.w;
            t = *(const float4*)&Bs[kt][tx * 4];      b[0]=t.x; b[1]=t.y; b[2]=t.z; b[3]=t.w;
            t = *(const float4*)&Bs[kt][64 + tx * 4]; b[4]=t.x; b[5]=t.y; b[6]=t.z; b[7]=t.w;
#pragma unroll
            for (int i = 0; i < 8; i++)
#pragma unroll
                for (int j = 0; j < 8; j++) acc[i][j] += a[i] * b[j];
        }
    }

    float qs = (z == qz) ? 0.125f * 1.4426950408889634f : 1.0f; // fold scale*log2e into q
    if (do_split && z < 2) {
        __nv_bfloat16* dh = (z == 0) ? g_qh : g_kh;
        __nv_bfloat16* dl = (z == 0) ? g_ql : g_kl;
#pragma unroll
        for (int i = 0; i < 8; i++) {
            int row = m0 + ((i < 4) ? (ty * 4 + i) : (64 + ty * 4 + i - 4));
            int l_idx = row >> 2, nb = row & 3;
#pragma unroll
            for (int jp = 0; jp < 4; jp++) {
                int j0 = 2 * jp;
                int col = e0 + ((j0 < 4) ? (tx * 4 + j0) : (64 + tx * 4 + j0 - 4));
                float v0 = (acc[i][j0]     + bias[col])     * qs;
                float v1 = (acc[i][j0 + 1] + bias[col + 1]) * qs;
                uint32_t hi, lo;
                split2(v0, v1, hi, lo);
                int hh = col >> 6, d = col & 63;
                size_t dstw = (((size_t)(nb * H + hh) * Ldim + l_idx) * HD + d) >> 1;
                ((uint32_t*)dh)[dstw] = hi;
                ((uint32_t*)dl)[dstw] = lo;
            }
        }
    } else {
#pragma unroll
        for (int i = 0; i < 8; i++) {
            int row = m0 + ((i < 4) ? (ty * 4 + i) : (64 + ty * 4 + i - 4));
#pragma unroll
            for (int j = 0; j < 8; j++) {
                int col = e0 + ((j < 4) ? (tx * 4 + j) : (64 + tx * 4 + j - 4));
                y[(size_t)row * E + col] = (acc[i][j] + bias[col]) * qs;
            }
        }
    }
}

// ---------------- prep: v -> transposed bf16 hi/lo [bh][d][L] ----------------
__global__ void __launch_bounds__(256) v_prep()
{
    __shared__ float vt[64][65];
    int bh = blockIdx.y;
    int s0 = blockIdx.x * 64;
    int nb = bh / H, h = bh % H;
    int t = threadIdx.x;
    {
        int s = t >> 2, dq = (t & 3) * 16;
        const float* src = g_v + ((size_t)(s0 + s) * Nb + nb) * E + h * HD + dq;
#pragma unroll
        for (int j = 0; j < 4; j++) {
            float4 v = *(const float4*)(src + j * 4);
            vt[s][dq + j * 4 + 0] = v.x;
            vt[s][dq + j * 4 + 1] = v.y;
            vt[s][dq + j * 4 + 2] = v.z;
            vt[s][dq + j * 4 + 3] = v.w;
        }
    }
    __syncthreads();
    {
        int d = t >> 2, sq = (t & 3) * 16;
        uint32_t hw[8], lw[8];
#pragma unroll
        for (int j = 0; j < 8; j++)
            split2(vt[sq + 2 * j][d], vt[sq + 2 * j + 1][d], hw[j], lw[j]);
        size_t dst = ((size_t)bh * HD + d) * Ldim + s0 + sq;
        ((uint4*)(g_vth + dst))[0] = make_uint4(hw[0], hw[1], hw[2], hw[3]);
        ((uint4*)(g_vth + dst))[1] = make_uint4(hw[4], hw[5], hw[6], hw[7]);
        ((uint4*)(g_vtl + dst))[0] = make_uint4(lw[0], lw[1], lw[2], lw[3]);
        ((uint4*)(g_vtl + dst))[1] = make_uint4(lw[4], lw[5], lw[6], lw[7]);
    }
}

// ================= warp-MMA flash attention ==================================
// grid (L/64, BH), 128 threads (4 warps, 16 q-rows each), BS=64,
// cp.async double-buffered KV, 90KB smem -> 2 CTAs/SM.
// QK^T: 3-pass bf16 split. PV: 2-pass (rounded-P with exact-l normalization).
#define SKB 144                 /* smem row stride bytes (72 bf16, pad) */
#define SQH 0
#define SQL 9216
#define SKV0 18432
#define STAGE_B 36864
#define KH_O 0
#define KL_O 9216
#define VH_O 18432
#define VL_O 27648
#define S_TOTAL3 (SKV0 + 2*STAGE_B)   /* 92160 */
#define NT (Ldim / 64)

__device__ __forceinline__ void kv_prefetch(uint32_t buf, int bh, int s0, int tid)
{
    int m = tid >> 1;                 // row 0..63
    int hf = tid & 1;                 // half-row: 64 bytes = 32 bf16
    uint32_t ro = (uint32_t)m * SKB + (uint32_t)hf * 64;
    const __nv_bfloat16* kh = g_kh + ((size_t)bh * Ldim + s0 + m) * HD + hf * 32;
    const __nv_bfloat16* kl = g_kl + ((size_t)bh * Ldim + s0 + m) * HD + hf * 32;
    const __nv_bfloat16* vh = g_vth + ((size_t)bh * HD + m) * Ldim + s0 + hf * 32;
    const __nv_bfloat16* vl = g_vtl + ((size_t)bh * HD + m) * Ldim + s0 + hf * 32;
#pragma unroll
    for (int c = 0; c < 4; c++) {
        cpa16(buf + KH_O + ro + c * 16, kh + c * 8);
        cpa16(buf + KL_O + ro + c * 16, kl + c * 8);
        cpa16(buf + VH_O + ro + c * 16, vh + c * 8);
        cpa16(buf + VL_O + ro + c * 16, vl + c * 8);
    }
}

__global__ void __launch_bounds__(128, 2) attn_mma3()
{
    extern __shared__ __align__(128) char smem[];
    uint32_t sb = smem_u32(smem);
    int tid = threadIdx.x;
    int wid = tid >> 5, lane = tid & 31;
    int bh = blockIdx.y;
    int nb = bh / H, h = bh % H;
    int q0 = blockIdx.x * 64;

    // stage-0 KV prefetch first (overlaps Q load)
    kv_prefetch(sb + SKV0, bh, 0, tid);
    CP_COMMIT();

    // load Q hi/lo (64 rows x 64): 128 threads x 64B per tile
    {
        int m = tid >> 1;
        int u0 = (tid & 1) * 4;
        uint32_t o = (uint32_t)m * SKB + (uint32_t)u0 * 16;
        const uint4* s = (const uint4*)(g_qh + ((size_t)bh * Ldim + q0 + m) * HD) + u0;
        uint4 a = s[0], b = s[1], c = s[2], d = s[3];
        STS128(sb + SQH + o,      a.x, a.y, a.z, a.w);
        STS128(sb + SQH + o + 16, b.x, b.y, b.z, b.w);
        STS128(sb + SQH + o + 32, c.x, c.y, c.z, c.w);
        STS128(sb + SQH + o + 48, d.x, d.y, d.z, d.w);
        s = (const uint4*)(g_ql + ((size_t)bh * Ldim + q0 + m) * HD) + u0;
        a = s[0]; b = s[1]; c = s[2]; d = s[3];
        STS128(sb + SQL + o,      a.x, a.y, a.z, a.w);
        STS128(sb + SQL + o + 16, b.x, b.y, b.z, b.w);
        STS128(sb + SQL + o + 32, c.x, c.y, c.z, c.w);
        STS128(sb + SQL + o + 48, d.x, d.y, d.z, d.w);
    }
    __syncthreads();

    // per-lane ldmatrix address components
    uint32_t qrow = (uint32_t)(16 * wid + (lane & 15)) * SKB + (uint32_t)(lane >> 4) * 16;
    uint32_t brow = (uint32_t)(((lane >> 4) * 8 + (lane & 7))) * SKB
                  + (uint32_t)((lane >> 3) & 1) * 16;

    // Q fragments held in registers for the whole loop
    uint32_t qfh[4][4], qfl[4][4];
#pragma unroll
    for (int k = 0; k < 4; k++) {
        ldm_x4(qfh[k], sb + SQH + qrow + k * 32);
        ldm_x4(qfl[k], sb + SQL + qrow + k * 32);
    }

    float Oa[8][4];
#pragma unroll
    for (int n = 0; n < 8; n++)
#pragma unroll
        for (int j = 0; j < 4; j++) Oa[n][j] = 0.f;
    float m_lo = -INFINITY, m_hi = -INFINITY, l_lo = 0.f, l_hi = 0.f;

    for (int t = 0; t < NT; t++) {
        uint32_t cb = sb + SKV0 + (uint32_t)(t & 1) * STAGE_B;
        if (t + 1 < NT) {
            kv_prefetch(sb + SKV0 + (uint32_t)((t + 1) & 1) * STAGE_B,
                        bh, (t + 1) * 64, tid);
            CP_COMMIT();
            CP_WAIT1();
        } else {
            CP_WAIT0();
        }
        __syncthreads();

        // ---- S = Q K^T (3-pass) --------------------------------------------
        float c[8][4];
#pragma unroll
        for (int n = 0; n < 8; n++)
#pragma unroll
            for (int j = 0; j < 4; j++) c[n][j] = 0.f;
#pragma unroll
        for (int np = 0; np < 4; np++) {
            uint32_t baseH = cb + KH_O + brow + np * (16 * SKB);
            uint32_t baseL = cb + KL_O + brow + np * (16 * SKB);
#pragma unroll
            for (int k = 0; k < 4; k++) {
                uint32_t bhh[4], bll[4];
                ldm_x4(bhh, baseH + k * 32);
                ldm_x4(bll, baseL + k * 32);
                mma16816(c[2 * np],     qfh[k], bhh);
                mma16816(c[2 * np],     qfh[k], bll);
                mma16816(c[2 * np],     qfl[k], bhh);
                mma16816(c[2 * np + 1], qfh[k], bhh + 2);
                mma16816(c[2 * np + 1], qfh[k], bll + 2);
                mma16816(c[2 * np + 1], qfl[k], bhh + 2);
            }
        }

        // ---- online softmax (quad-local rows) -------------------------------
        float mn_lo = m_lo, mn_hi = m_hi;
#pragma unroll
        for (int n = 0; n < 8; n++) {
            mn_lo = fmaxf(mn_lo, fmaxf(c[n][0], c[n][1]));
            mn_hi = fmaxf(mn_hi, fmaxf(c[n][2], c[n][3]));
        }
        mn_lo = fmaxf(mn_lo, __shfl_xor_sync(0xffffffffu, mn_lo, 1));
        mn_lo = fmaxf(mn_lo, __shfl_xor_sync(0xffffffffu, mn_lo, 2));
        mn_hi = fmaxf(mn_hi, __shfl_xor_sync(0xffffffffu, mn_hi, 1));
        mn_hi = fmaxf(mn_hi, __shfl_xor_sync(0xffffffffu, mn_hi, 2));
        float corr_lo = ex2f(m_lo - mn_lo);
        float corr_hi = ex2f(m_hi - mn_hi);
        m_lo = mn_lo; m_hi = mn_hi;
        l_lo *= corr_lo; l_hi *= corr_hi;
#pragma unroll
        for (int n = 0; n < 8; n++) {
            Oa[n][0] *= corr_lo; Oa[n][1] *= corr_lo;
            Oa[n][2] *= corr_hi; Oa[n][3] *= corr_hi;
        }
        // exp -> round to bf16 P; accumulate l from ROUNDED values (exact norm)
        uint32_t ph[4][4];
#pragma unroll
        for (int n = 0; n < 8; n++) {
            float p0 = ex2f(c[n][0] - mn_lo);
            float p1 = ex2f(c[n][1] - mn_lo);
            float p2 = ex2f(c[n][2] - mn_hi);
            float p3 = ex2f(c[n][3] - mn_hi);
            __nv_bfloat162 h01 = __floats2bfloat162_rn(p0, p1);
            __nv_bfloat162 h23 = __floats2bfloat162_rn(p2, p3);
            l_lo += __bfloat162float(h01.x) + __bfloat162float(h01.y);
            l_hi += __bfloat162float(h23.x) + __bfloat162float(h23.y);
            int kc = n >> 1, o = (n & 1) * 2;
            ph[kc][o]     = *reinterpret_cast<uint32_t*>(&h01);
            ph[kc][o + 1] = *reinterpret_cast<uint32_t*>(&h23);
        }

        // ---- O += P (Vh + Vl) : 2-pass ---------------------------------------
#pragma unroll
        for (int np = 0; np < 4; np++) {
            uint32_t baseH = cb + VH_O + brow + np * (16 * SKB);
            uint32_t baseL = cb + VL_O + brow + np * (16 * SKB);
#pragma unroll
            for (int k = 0; k < 4; k++) {
                uint32_t vhh[4], vll[4];
                ldm_x4(vhh, baseH + k * 32);
                ldm_x4(vll, baseL + k * 32);
                mma16816(Oa[2 * np],     ph[k], vhh);
                mma16816(Oa[2 * np],     ph[k], vll);
                mma16816(Oa[2 * np + 1], ph[k], vhh + 2);
                mma16816(Oa[2 * np + 1], ph[k], vll + 2);
            }
        }
        __syncthreads();
    }

    // ---- epilogue -------------------------------------------------------------
    l_lo += __shfl_xor_sync(0xffffffffu, l_lo, 1);
    l_lo += __shfl_xor_sync(0xffffffffu, l_lo, 2);
    l_hi += __shfl_xor_sync(0xffffffffu, l_hi, 1);
    l_hi += __shfl_xor_sync(0xffffffffu, l_hi, 2);
    float inv_lo = 1.f / l_lo, inv_hi = 1.f / l_hi;

    int r = lane >> 2, cc = (lane & 3) * 2;
    float* o_lo = g_o + ((size_t)(q0 + 16 * wid + r) * Nb + nb) * E + h * HD;
    float* o_hi = g_o + ((size_t)(q0 + 16 * wid + r + 8) * Nb + nb) * E + h * HD;
#pragma unroll
    for (int n = 0; n < 8; n++) {
        int d = n * 8 + cc;
        float2 vlo = make_float2(Oa[n][0] * inv_lo, Oa[n][1] * inv_lo);
        float2 vhi = make_float2(Oa[n][2] * inv_hi, Oa[n][3] * inv_hi);
        *(float2*)(o_lo + d) = vlo;
        *(float2*)(o_hi + d) = vhi;
    }
}

// ---------------- launcher ---------------------------------------------------
extern "C" void kernel_launch(void* const* d_in, const int* in_sizes, int n_in,
                              void* d_out, int out_size)
{
    const float* query = (const float*)d_in[0];
    const float* key   = (const float*)d_in[1];
    const float* value = (const float*)d_in[2];
    const float* in_w  = (const float*)d_in[3];
    const float* in_b  = (const float*)d_in[4];
    const float* q_dn  = (const float*)d_in[5];
    const float* q_up  = (const float*)d_in[6];
    const float* k_dn  = (const float*)d_in[7];
    const float* k_up  = (const float*)d_in[8];
    const float* v_dn  = (const float*)d_in[9];
    const float* v_up  = (const float*)d_in[10];
    const float* out_w = (const float*)d_in[11];
    const float* out_b = (const float*)d_in[12];
    const float* o_dn  = (const float*)d_in[13];
    const float* o_up  = (const float*)d_in[14];

    float *p_weff, *p_v, *p_o;
    cudaGetSymbolAddress((void**)&p_weff, g_weff);
    cudaGetSymbolAddress((void**)&p_v, g_v);
    cudaGetSymbolAddress((void**)&p_o, g_o);

    cudaFuncSetAttribute(attn_mma3,
                         cudaFuncAttributeMaxDynamicSharedMemorySize, S_TOTAL3);

    // 1) fold LoRA into effective weights
    weff_kernel<<<dim3(EE / 256, 4), 256>>>(in_w, out_w,
                                            q_dn, q_up, k_dn, k_up,
                                            v_dn, v_up, o_dn, o_up);
    // 2) q,k,v projections; q,k split-written as bf16 hi/lo, v fp32
    gemm_proj<<<dim3(E / 128, Mrows / 128, 3), 256>>>(
        query, key, value, p_weff, in_b, p_v, p_v, p_v, /*qz=*/0, /*split=*/1);
    // 3) v transpose + split
    v_prep<<<dim3(Ldim / 64, BH), 256>>>();
    // 4) warp-MMA flash attention (launch #4 -> profiled)
    attn_mma3<<<dim3(Ldim / 64, BH), 128, S_TOTAL3>>>();
    // 5) output projection -> d_out
    gemm_proj<<<dim3(E / 128, Mrows / 128, 1), 256>>>(
        p_o, p_o, p_o, p_weff + 3 * (size_t)EE, out_b,
        (float*)d_out, (float*)d_out, (float*)d_out, /*qz=*/-1, /*split=*/0);
}